// round 3
// baseline (speedup 1.0000x reference)
#include <cuda_runtime.h>
#include <math.h>

// ---------------- problem constants ----------------
#define BW_   512              // total windows
#define NW_   64               // mask batch
#define N_    343              // tokens per window
#define NPAD  352              // padded to 11*32
#define DIM_  96
#define HEADS 3
#define HD    32
#define NN_   (N_ * N_)        // 117649
#define ROWS_TOT (BW_ * N_)    // 175616

// ---------------- device scratch (allocation-free rule: __device__ globals) ----------------
__device__ float g_q [BW_ * HEADS * N_ * HD];   // 67.4 MB
__device__ float g_k [BW_ * HEADS * N_ * HD];
__device__ float g_v [BW_ * HEADS * N_ * HD];
__device__ float g_ao[ROWS_TOT * DIM_];          // attention output, [m][96]
__device__ float g_bias[HEADS * NN_];            // rel bias per head, 1.4 MB

// ---------------- kernel 1: relative-position bias gather ----------------
__global__ void bias_kernel(const int* __restrict__ rpi, const float* __restrict__ table) {
    int idx = blockIdx.x * blockDim.x + threadIdx.x;
    if (idx < NN_) {
        int r = rpi[idx];
#pragma unroll
        for (int h = 0; h < HEADS; h++)
            g_bias[h * NN_ + idx] = table[r * HEADS + h];
    }
}

// ---------------- kernel 2: QKV GEMM  out[m][c] = sum_k x[m][k]*Wqkv[c][k] + b[c] ----------------
// grid: (1372, 3). block tile 128 rows x 96 cols (one "which" slice per blockIdx.y).
__global__ __launch_bounds__(256) void qkv_gemm(const float* __restrict__ x,
                                                const float* __restrict__ W,
                                                const float* __restrict__ bias) {
    extern __shared__ float sm[];
    float* xs = sm;               // [128][97]
    float* ws = sm + 128 * 97;    // [96][97]
    const int tid   = threadIdx.x;
    const int which = blockIdx.y;
    const int m0    = blockIdx.x * 128;

    // stage x tile (128x96) via float4
    {
        const float4* xg = (const float4*)(x + (size_t)m0 * 96);
        for (int i = tid; i < 128 * 24; i += 256) {
            int r = i / 24, c4 = i % 24;
            float4 v = xg[r * 24 + c4];
            float* d = xs + r * 97 + c4 * 4;
            d[0] = v.x; d[1] = v.y; d[2] = v.z; d[3] = v.w;
        }
    }
    // stage W slice (96x96)
    {
        const float4* wg = (const float4*)(W + (size_t)which * 96 * 96);
        for (int i = tid; i < 96 * 24; i += 256) {
            int r = i / 24, c4 = i % 24;
            float4 v = wg[r * 24 + c4];
            float* d = ws + r * 97 + c4 * 4;
            d[0] = v.x; d[1] = v.y; d[2] = v.z; d[3] = v.w;
        }
    }
    __syncthreads();

    const int tx = tid & 15, ty = tid >> 4;
    float acc[8][6];
#pragma unroll
    for (int i = 0; i < 8; i++)
#pragma unroll
        for (int j = 0; j < 6; j++) acc[i][j] = 0.0f;

#pragma unroll 4
    for (int k = 0; k < 96; k++) {
        float a[8], b[6];
#pragma unroll
        for (int i = 0; i < 8; i++) a[i] = xs[(ty * 8 + i) * 97 + k];
#pragma unroll
        for (int j = 0; j < 6; j++) b[j] = ws[(tx * 6 + j) * 97 + k];
#pragma unroll
        for (int i = 0; i < 8; i++)
#pragma unroll
            for (int j = 0; j < 6; j++) acc[i][j] += a[i] * b[j];
    }

    float* base = (which == 0) ? g_q : (which == 1) ? g_k : g_v;
#pragma unroll
    for (int i = 0; i < 8; i++) {
        int m = m0 + ty * 8 + i;
        int bw = m / N_, n = m - bw * N_;
#pragma unroll
        for (int j = 0; j < 6; j++) {
            int c = tx * 6 + j;            // 0..95
            int h = c >> 5, d = c & 31;
            base[(((size_t)bw * HEADS + h) * N_ + n) * HD + d] = acc[i][j] + bias[which * 96 + c];
        }
    }
}

// ---------------- kernel 3: attention, one CTA per (window, head) ----------------
// q/k L2-normalization is fused into the staging loop (warp per row, shuffle reduce).
// smem: ks/vs/qs [352][33] + ps [32][352]  = 184448 B
__global__ __launch_bounds__(256) void attn_kernel(const float* __restrict__ mask,
                                                   const float* __restrict__ logit_scale) {
    extern __shared__ float sm[];
    float* ks = sm;
    float* vs = ks + NPAD * 33;
    float* qs = vs + NPAD * 33;
    float* ps = qs + NPAD * 33;   // [32][NPAD], 16B-aligned (offset 34848 floats)

    const int bx = blockIdx.x;
    const int b  = bx / HEADS;
    const int h  = bx - b * HEADS;
    const int w  = b & (NW_ - 1);
    const int tid = threadIdx.x;
    const int ty = tid >> 5, tx = tid & 31;

    const size_t bh = (size_t)b * HEADS + h;
    const float* qg = g_q + bh * N_ * HD;
    const float* kg = g_k + bh * N_ * HD;
    const float* vg = g_v + bh * N_ * HD;

    // stage: warp per row (lane = dim), fused L2 normalization of q and k.
    // rows 343..351 zero-padded.
    for (int r = ty; r < NPAD; r += 8) {
        float qv = 0.f, kv = 0.f, vv = 0.f;
        if (r < N_) {
            int off = r * HD + tx;
            qv = qg[off]; kv = kg[off]; vv = vg[off];
        }
        float qss = qv * qv, kss = kv * kv;
#pragma unroll
        for (int o = 16; o; o >>= 1) {
            qss += __shfl_xor_sync(0xffffffffu, qss, o);
            kss += __shfl_xor_sync(0xffffffffu, kss, o);
        }
        float qinv = 1.0f / fmaxf(sqrtf(qss), 1e-12f);
        float kinv = 1.0f / fmaxf(sqrtf(kss), 1e-12f);
        qs[r * 33 + tx] = qv * qinv;
        ks[r * 33 + tx] = kv * kinv;
        vs[r * 33 + tx] = vv;
    }
    __syncthreads();

    const float scl = fminf(__expf(logit_scale[h]), 100.0f);
    const float* maskb = mask + (size_t)w * NN_;
    const float* biasb = g_bias + (size_t)h * NN_;

    for (int i0 = 0; i0 < NPAD; i0 += 32) {
        // ---- Phase A: scores, 4 rows per warp, lanes strided over j ----
        float acc[4][11];
#pragma unroll
        for (int rr = 0; rr < 4; rr++)
#pragma unroll
            for (int t = 0; t < 11; t++) acc[rr][t] = 0.0f;

#pragma unroll 2
        for (int d = 0; d < 32; d++) {
            float qv[4];
#pragma unroll
            for (int rr = 0; rr < 4; rr++) qv[rr] = qs[(i0 + ty * 4 + rr) * 33 + d];
#pragma unroll
            for (int t = 0; t < 11; t++) {
                float kv = ks[(tx + 32 * t) * 33 + d];
#pragma unroll
                for (int rr = 0; rr < 4; rr++) acc[rr][t] += qv[rr] * kv;
            }
        }

        // ---- softmax (warp-local; rows are warp-private) ----
#pragma unroll
        for (int rr = 0; rr < 4; rr++) {
            int i  = i0 + ty * 4 + rr;
            int ic = (i < N_) ? i : (N_ - 1);
            const float* brow = biasb + (size_t)ic * N_;
            const float* mrow = maskb + (size_t)ic * N_;
            float mx = -1e30f;
#pragma unroll
            for (int t = 0; t < 11; t++) {
                int j = tx + 32 * t;
                float s = (j < N_) ? (acc[rr][t] * scl + brow[j] + mrow[j]) : -1e30f;
                acc[rr][t] = s;
                mx = fmaxf(mx, s);
            }
#pragma unroll
            for (int o = 16; o; o >>= 1) mx = fmaxf(mx, __shfl_xor_sync(0xffffffffu, mx, o));
            float sum = 0.0f;
#pragma unroll
            for (int t = 0; t < 11; t++) {
                int j = tx + 32 * t;
                float e = (j < N_) ? __expf(acc[rr][t] - mx) : 0.0f;
                acc[rr][t] = e;
                sum += e;
            }
#pragma unroll
            for (int o = 16; o; o >>= 1) sum += __shfl_xor_sync(0xffffffffu, sum, o);
            float inv = 1.0f / sum;
#pragma unroll
            for (int t = 0; t < 11; t++)
                ps[(ty * 4 + rr) * NPAD + tx + 32 * t] = acc[rr][t] * inv;
        }
        __syncwarp();

        // ---- Phase B: O = P @ V, lane = d, float4 broadcast p loads ----
        float o4[4] = {0.f, 0.f, 0.f, 0.f};
#pragma unroll 2
        for (int j0 = 0; j0 < NPAD; j0 += 4) {
            float pr[4][4];
#pragma unroll
            for (int rr = 0; rr < 4; rr++) {
                float4 t4 = *(const float4*)&ps[(ty * 4 + rr) * NPAD + j0];
                pr[rr][0] = t4.x; pr[rr][1] = t4.y; pr[rr][2] = t4.z; pr[rr][3] = t4.w;
            }
#pragma unroll
            for (int jj = 0; jj < 4; jj++) {
                float vv = vs[(j0 + jj) * 33 + tx];
#pragma unroll
                for (int rr = 0; rr < 4; rr++) o4[rr] += pr[rr][jj] * vv;
            }
        }
#pragma unroll
        for (int rr = 0; rr < 4; rr++) {
            int i = i0 + ty * 4 + rr;
            if (i < N_)
                g_ao[((size_t)b * N_ + i) * DIM_ + h * HD + tx] = o4[rr];
        }
        __syncwarp();
    }
}

// ---------------- kernel 4: output projection GEMM (N=96) ----------------
__global__ __launch_bounds__(256) void proj_gemm(const float* __restrict__ W,
                                                 const float* __restrict__ bias,
                                                 float* __restrict__ out) {
    extern __shared__ float sm[];
    float* xs = sm;               // [128][97]
    float* ws = sm + 128 * 97;    // [96][97]
    const int tid = threadIdx.x;
    const int m0  = blockIdx.x * 128;

    {
        const float4* xg = (const float4*)(g_ao + (size_t)m0 * 96);
        for (int i = tid; i < 128 * 24; i += 256) {
            int r = i / 24, c4 = i % 24;
            float4 v = xg[r * 24 + c4];
            float* d = xs + r * 97 + c4 * 4;
            d[0] = v.x; d[1] = v.y; d[2] = v.z; d[3] = v.w;
        }
    }
    {
        const float4* wg = (const float4*)W;
        for (int i = tid; i < 96 * 24; i += 256) {
            int r = i / 24, c4 = i % 24;
            float4 v = wg[r * 24 + c4];
            float* d = ws + r * 97 + c4 * 4;
            d[0] = v.x; d[1] = v.y; d[2] = v.z; d[3] = v.w;
        }
    }
    __syncthreads();

    const int tx = tid & 15, ty = tid >> 4;
    float acc[8][6];
#pragma unroll
    for (int i = 0; i < 8; i++)
#pragma unroll
        for (int j = 0; j < 6; j++) acc[i][j] = 0.0f;

#pragma unroll 4
    for (int k = 0; k < 96; k++) {
        float a[8], b[6];
#pragma unroll
        for (int i = 0; i < 8; i++) a[i] = xs[(ty * 8 + i) * 97 + k];
#pragma unroll
        for (int j = 0; j < 6; j++) b[j] = ws[(tx * 6 + j) * 97 + k];
#pragma unroll
        for (int i = 0; i < 8; i++)
#pragma unroll
            for (int j = 0; j < 6; j++) acc[i][j] += a[i] * b[j];
    }

#pragma unroll
    for (int i = 0; i < 8; i++) {
        int m = m0 + ty * 8 + i;
#pragma unroll
        for (int j = 0; j < 6; j++) {
            int c = tx * 6 + j;
            out[(size_t)m * 96 + c] = acc[i][j] + bias[c];
        }
    }
}

// ---------------- launch ----------------
extern "C" void kernel_launch(void* const* d_in, const int* in_sizes, int n_in,
                              void* d_out, int out_size) {
    const float* x     = (const float*)d_in[0];
    const float* mask  = (const float*)d_in[1];
    const float* Wqkv  = (const float*)d_in[2];
    const float* bqkv  = (const float*)d_in[3];
    const float* Wproj = (const float*)d_in[4];
    const float* bproj = (const float*)d_in[5];
    const float* ls    = (const float*)d_in[6];
    const float* table = (const float*)d_in[7];
    const int*   rpi   = (const int*)d_in[8];
    float* out = (float*)d_out;

    const int smG = (128 * 97 + 96 * 97) * 4;                  // 86912 B
    const int smA = (3 * NPAD * 33 + 32 * NPAD) * 4;           // 184448 B
    cudaFuncSetAttribute(qkv_gemm,  cudaFuncAttributeMaxDynamicSharedMemorySize, smG);
    cudaFuncSetAttribute(proj_gemm, cudaFuncAttributeMaxDynamicSharedMemorySize, smG);
    cudaFuncSetAttribute(attn_kernel, cudaFuncAttributeMaxDynamicSharedMemorySize, smA);

    bias_kernel<<<(NN_ + 255) / 256, 256>>>(rpi, table);
    qkv_gemm<<<dim3(ROWS_TOT / 128, 3), 256, smG>>>(x, Wqkv, bqkv);
    attn_kernel<<<BW_ * HEADS, 256, smA>>>(mask, ls);
    proj_gemm<<<ROWS_TOT / 128, 256, smG>>>(Wproj, bproj, out);
}

// round 6
// speedup vs baseline: 1.0968x; 1.0968x over previous
#include <cuda_runtime.h>
#include <math.h>

// ---------------- problem constants ----------------
#define BW_   512              // total windows
#define NW_   64               // mask batch
#define N_    343              // tokens per window
#define NPAD  352              // padded to 11*32
#define PSW   344              // ps row stride (mult of 4)
#define DIM_  96
#define HEADS 3
#define HD    32
#define NN_   (N_ * N_)        // 117649
#define ROWS_TOT (BW_ * N_)    // 175616

// smem float offsets for attn
#define KS_OFF 0
#define VS_OFF (NPAD * 33)
#define QS_OFF (2 * NPAD * 33)
#define PS_OFF (2 * NPAD * 33 + NPAD * 36)

// ---------------- device scratch ----------------
__device__ float g_q [BW_ * HEADS * N_ * HD];
__device__ float g_k [BW_ * HEADS * N_ * HD];
__device__ float g_v [BW_ * HEADS * N_ * HD];
__device__ float g_ao[ROWS_TOT * DIM_];
__device__ float g_bias[HEADS * NN_];

// ---------------- kernel 1: relative-position bias gather ----------------
__global__ void bias_kernel(const int* __restrict__ rpi, const float* __restrict__ table) {
    int idx = blockIdx.x * blockDim.x + threadIdx.x;
    if (idx < NN_) {
        int r = rpi[idx];
#pragma unroll
        for (int h = 0; h < HEADS; h++)
            g_bias[h * NN_ + idx] = table[r * HEADS + h];
    }
}

// ---------------- GEMM core (k-major smem, vectorized operand loads) ----------------
// xs_t: [96][132]  (k-major activations, 128 rows)
// ws_t: [96][100]  (k-major weights, 96 outputs)
__device__ __forceinline__ void gemm_core(const float* __restrict__ xg4,   // 128x96 tile (row-major)
                                          const float* __restrict__ wg4,   // 96x96 slice (row-major)
                                          float* xs_t, float* ws_t,
                                          float acc[8][6], int tid) {
    {
        const float4* xg = (const float4*)xg4;
        for (int i = tid; i < 128 * 24; i += 256) {
            int r = i / 24, c4 = i % 24;
            float4 v = xg[r * 24 + c4];
            xs_t[(c4 * 4 + 0) * 132 + r] = v.x;
            xs_t[(c4 * 4 + 1) * 132 + r] = v.y;
            xs_t[(c4 * 4 + 2) * 132 + r] = v.z;
            xs_t[(c4 * 4 + 3) * 132 + r] = v.w;
        }
    }
    {
        const float4* wg = (const float4*)wg4;
        for (int i = tid; i < 96 * 24; i += 256) {
            int r = i / 24, c4 = i % 24;
            float4 v = wg[r * 24 + c4];
            ws_t[(c4 * 4 + 0) * 100 + r] = v.x;
            ws_t[(c4 * 4 + 1) * 100 + r] = v.y;
            ws_t[(c4 * 4 + 2) * 100 + r] = v.z;
            ws_t[(c4 * 4 + 3) * 100 + r] = v.w;
        }
    }
    __syncthreads();

    const int tx = tid & 15, ty = tid >> 4;
#pragma unroll
    for (int i = 0; i < 8; i++)
#pragma unroll
        for (int j = 0; j < 6; j++) acc[i][j] = 0.0f;

#pragma unroll 4
    for (int k = 0; k < 96; k++) {
        float4 a0 = *(const float4*)&xs_t[k * 132 + ty * 8];
        float4 a1 = *(const float4*)&xs_t[k * 132 + ty * 8 + 4];
        float2 b0 = *(const float2*)&ws_t[k * 100 + tx * 6];
        float2 b1 = *(const float2*)&ws_t[k * 100 + tx * 6 + 2];
        float2 b2 = *(const float2*)&ws_t[k * 100 + tx * 6 + 4];
        float a[8] = {a0.x, a0.y, a0.z, a0.w, a1.x, a1.y, a1.z, a1.w};
        float b[6] = {b0.x, b0.y, b1.x, b1.y, b2.x, b2.y};
#pragma unroll
        for (int i = 0; i < 8; i++)
#pragma unroll
            for (int j = 0; j < 6; j++) acc[i][j] = fmaf(a[i], b[j], acc[i][j]);
    }
}

// ---------------- kernel 2: QKV GEMM ----------------
__global__ __launch_bounds__(256, 2) void qkv_gemm(const float* __restrict__ x,
                                                   const float* __restrict__ W,
                                                   const float* __restrict__ bias) {
    extern __shared__ float sm[];
    float* xs_t = sm;                 // 96*132
    float* ws_t = sm + 96 * 132;      // 96*100
    const int tid   = threadIdx.x;
    const int which = blockIdx.y;
    const int m0    = blockIdx.x * 128;

    float acc[8][6];
    gemm_core(x + (size_t)m0 * 96, W + (size_t)which * 96 * 96, xs_t, ws_t, acc, tid);

    const int tx = tid & 15, ty = tid >> 4;
    float* base = (which == 0) ? g_q : (which == 1) ? g_k : g_v;
#pragma unroll
    for (int i = 0; i < 8; i++) {
        int m = m0 + ty * 8 + i;
        int bw = m / N_, n = m - bw * N_;
#pragma unroll
        for (int j = 0; j < 6; j++) {
            int c = tx * 6 + j;
            int h = c >> 5, d = c & 31;
            base[(((size_t)bw * HEADS + h) * N_ + n) * HD + d] = acc[i][j] + bias[which * 96 + c];
        }
    }
}

// ---------------- attn tile worker ----------------
// ps row ownership is warp-constant: warp ty ALWAYS uses ps rows [ty*8, ty*8+RPW).
// (R5 bug: the tail tile used ty*4+rr, stealing rows another warp might still be
//  reading in its Phase B — cross-warp WAR race with no intervening syncthreads.)
template<int RPW>
__device__ __forceinline__ void attn_tile(int i0, float* sm,
                                          const float* __restrict__ biasb,
                                          const float* __restrict__ maskb,
                                          float scl, int b, int h, int ty, int tx) {
    float* ks = sm + KS_OFF;
    float* vs = sm + VS_OFF;
    float* qs = sm + QS_OFF;
    float* ps = sm + PS_OFF;

    // ---- Phase A: S = Q K^T, RPW rows per warp, lanes strided over j ----
    float acc[RPW][11];
#pragma unroll
    for (int rr = 0; rr < RPW; rr++)
#pragma unroll
        for (int t = 0; t < 11; t++) acc[rr][t] = 0.0f;

#pragma unroll
    for (int d0 = 0; d0 < 32; d0 += 4) {
        float qa[RPW][4];
#pragma unroll
        for (int rr = 0; rr < RPW; rr++) {
            int row = i0 + ty * RPW + rr;
            row = (row < NPAD) ? row : 0;
            float4 q4 = *(const float4*)&qs[row * 36 + d0];   // broadcast
            qa[rr][0] = q4.x; qa[rr][1] = q4.y; qa[rr][2] = q4.z; qa[rr][3] = q4.w;
        }
#pragma unroll
        for (int dd = 0; dd < 4; dd++) {
#pragma unroll
            for (int t = 0; t < 11; t++) {
                float kv = ks[(tx + 32 * t) * 33 + d0 + dd];
#pragma unroll
                for (int rr = 0; rr < RPW; rr++)
                    acc[rr][t] = fmaf(qa[rr][dd], kv, acc[rr][t]);
            }
        }
    }

    // ---- softmax (warp-local rows) ----
#pragma unroll
    for (int rr = 0; rr < RPW; rr++) {
        int i  = i0 + ty * RPW + rr;
        int ic = (i < N_) ? i : (N_ - 1);
        const float* brow = biasb + (size_t)ic * N_;
        const float* mrow = maskb + (size_t)ic * N_;
        float bm[11];
#pragma unroll
        for (int t = 0; t < 11; t++) {
            int j = tx + 32 * t;
            bm[t] = (j < N_) ? (brow[j] + mrow[j]) : -1e30f;
        }
        float mx = -1e30f;
#pragma unroll
        for (int t = 0; t < 11; t++) {
            int j = tx + 32 * t;
            float s = (j < N_) ? fmaf(acc[rr][t], scl, bm[t]) : -1e30f;
            acc[rr][t] = s;
            mx = fmaxf(mx, s);
        }
#pragma unroll
        for (int o = 16; o; o >>= 1) mx = fmaxf(mx, __shfl_xor_sync(0xffffffffu, mx, o));
        float sum = 0.0f;
#pragma unroll
        for (int t = 0; t < 11; t++) {
            int j = tx + 32 * t;
            float e = (j < N_) ? __expf(acc[rr][t] - mx) : 0.0f;
            acc[rr][t] = e;
            sum += e;
        }
#pragma unroll
        for (int o = 16; o; o >>= 1) sum += __shfl_xor_sync(0xffffffffu, sum, o);
        float inv = 1.0f / sum;
#pragma unroll
        for (int t = 0; t < 11; t++) {
            int j = tx + 32 * t;
            if (j < PSW)
                ps[(ty * 8 + rr) * PSW + j] = acc[rr][t] * inv;   // warp-constant row
        }
    }
    __syncwarp();

    // ---- Phase B: O = P V ----
    float o[RPW];
#pragma unroll
    for (int rr = 0; rr < RPW; rr++) o[rr] = 0.0f;

#pragma unroll 2
    for (int j0 = 0; j0 < PSW; j0 += 4) {
        float pa[RPW][4];
#pragma unroll
        for (int rr = 0; rr < RPW; rr++) {
            float4 p4 = *(const float4*)&ps[(ty * 8 + rr) * PSW + j0];  // warp-constant row
            pa[rr][0] = p4.x; pa[rr][1] = p4.y; pa[rr][2] = p4.z; pa[rr][3] = p4.w;
        }
#pragma unroll
        for (int jj = 0; jj < 4; jj++) {
            float vv = vs[(j0 + jj) * 33 + tx];
#pragma unroll
            for (int rr = 0; rr < RPW; rr++)
                o[rr] = fmaf(pa[rr][jj], vv, o[rr]);
        }
    }
#pragma unroll
    for (int rr = 0; rr < RPW; rr++) {
        int i = i0 + ty * RPW + rr;
        if (i < N_)
            g_ao[((size_t)b * N_ + i) * DIM_ + h * HD + tx] = o[rr];
    }
    __syncwarp();
}

// ---------------- kernel 3: attention ----------------
// smem: ks/vs [352][33], qs [352][36], ps [64][344]  = 231680 B
__global__ __launch_bounds__(256) void attn_kernel(const float* __restrict__ mask,
                                                   const float* __restrict__ logit_scale) {
    extern __shared__ float sm[];
    float* ks = sm + KS_OFF;
    float* vs = sm + VS_OFF;
    float* qs = sm + QS_OFF;

    const int bx = blockIdx.x;
    const int b  = bx / HEADS;
    const int h  = bx - b * HEADS;
    const int w  = b & (NW_ - 1);
    const int tid = threadIdx.x;
    const int ty = tid >> 5, tx = tid & 31;

    const size_t bh = (size_t)b * HEADS + h;
    const float* qg = g_q + bh * N_ * HD;
    const float* kg = g_k + bh * N_ * HD;
    const float* vg = g_v + bh * N_ * HD;

    // stage: warp per row (lane = dim), fused q/k L2 normalization
    for (int r = ty; r < NPAD; r += 8) {
        float qv = 0.f, kv = 0.f, vv = 0.f;
        if (r < N_) {
            int off = r * HD + tx;
            qv = qg[off]; kv = kg[off]; vv = vg[off];
        }
        float qss = qv * qv, kss = kv * kv;
#pragma unroll
        for (int o = 16; o; o >>= 1) {
            qss += __shfl_xor_sync(0xffffffffu, qss, o);
            kss += __shfl_xor_sync(0xffffffffu, kss, o);
        }
        float qinv = 1.0f / fmaxf(sqrtf(qss), 1e-12f);
        float kinv = 1.0f / fmaxf(sqrtf(kss), 1e-12f);
        qs[r * 36 + tx] = qv * qinv;
        ks[r * 33 + tx] = kv * kinv;
        vs[r * 33 + tx] = vv;
    }
    __syncthreads();

    const float scl = fminf(__expf(logit_scale[h]), 100.0f);
    const float* maskb = mask + (size_t)w * NN_;
    const float* biasb = g_bias + (size_t)h * NN_;

    // 5 tiles of 64 rows (8 rows/warp), then one 32-row tile (4 rows/warp)
#pragma unroll 1
    for (int i0 = 0; i0 < 320; i0 += 64)
        attn_tile<8>(i0, sm, biasb, maskb, scl, b, h, ty, tx);
    attn_tile<4>(320, sm, biasb, maskb, scl, b, h, ty, tx);
}

// ---------------- kernel 4: output projection ----------------
__global__ __launch_bounds__(256, 2) void proj_gemm(const float* __restrict__ W,
                                                    const float* __restrict__ bias,
                                                    float* __restrict__ out) {
    extern __shared__ float sm[];
    float* xs_t = sm;
    float* ws_t = sm + 96 * 132;
    const int tid = threadIdx.x;
    const int m0  = blockIdx.x * 128;

    float acc[8][6];
    gemm_core(g_ao + (size_t)m0 * 96, W, xs_t, ws_t, acc, tid);

    const int tx = tid & 15, ty = tid >> 4;
#pragma unroll
    for (int i = 0; i < 8; i++) {
        int m = m0 + ty * 8 + i;
#pragma unroll
        for (int j = 0; j < 6; j++) {
            int c = tx * 6 + j;
            out[(size_t)m * 96 + c] = acc[i][j] + bias[c];
        }
    }
}

// ---------------- launch ----------------
extern "C" void kernel_launch(void* const* d_in, const int* in_sizes, int n_in,
                              void* d_out, int out_size) {
    const float* x     = (const float*)d_in[0];
    const float* mask  = (const float*)d_in[1];
    const float* Wqkv  = (const float*)d_in[2];
    const float* bqkv  = (const float*)d_in[3];
    const float* Wproj = (const float*)d_in[4];
    const float* bproj = (const float*)d_in[5];
    const float* ls    = (const float*)d_in[6];
    const float* table = (const float*)d_in[7];
    const int*   rpi   = (const int*)d_in[8];
    float* out = (float*)d_out;

    const int smG = (96 * 132 + 96 * 100) * 4;                 // 89088 B
    const int smA = (2 * NPAD * 33 + NPAD * 36 + 64 * PSW) * 4; // 231680 B
    cudaFuncSetAttribute(qkv_gemm,  cudaFuncAttributeMaxDynamicSharedMemorySize, smG);
    cudaFuncSetAttribute(proj_gemm, cudaFuncAttributeMaxDynamicSharedMemorySize, smG);
    cudaFuncSetAttribute(attn_kernel, cudaFuncAttributeMaxDynamicSharedMemorySize, smA);

    bias_kernel<<<(NN_ + 255) / 256, 256>>>(rpi, table);
    qkv_gemm<<<dim3(ROWS_TOT / 128, 3), 256, smG>>>(x, Wqkv, bqkv);
    attn_kernel<<<BW_ * HEADS, 256, smA>>>(mask, ls);
    proj_gemm<<<ROWS_TOT / 128, 256, smG>>>(Wproj, bproj, out);
}

// round 8
// speedup vs baseline: 1.1410x; 1.0403x over previous
#include <cuda_runtime.h>
#include <math.h>

// ---------------- problem constants ----------------
#define BW_   512              // total windows
#define NW_   64               // mask batch
#define N_    343              // tokens per window
#define NPAD  352              // padded loop bound (11*32)
#define NROWS 344              // smem rows actually stored
#define PSW   344              // ps / bm row stride (mult of 4)
#define DIM_  96
#define HEADS 3
#define HD    32
#define NN_   (N_ * N_)        // 117649
#define ROWS_TOT (BW_ * N_)    // 175616

// smem float offsets for attn (ks stride 36, vs stride 32, qs stride 36, ps 64x344)
#define KS_OFF 0
#define VS_OFF (NROWS * 36)
#define QS_OFF (NROWS * 36 + NROWS * 32)
#define PS_OFF (2 * NROWS * 36 + NROWS * 32)
#define SM_FLOATS (PS_OFF + 64 * PSW)      // 57792 floats = 231168 B

// ---------------- device scratch ----------------
__device__ float g_q [BW_ * HEADS * N_ * HD];
__device__ float g_k [BW_ * HEADS * N_ * HD];
__device__ float g_v [BW_ * HEADS * N_ * HD];
__device__ float g_ao[ROWS_TOT * DIM_];
__device__ float g_bm[(size_t)NW_ * HEADS * N_ * PSW];   // bias+mask, padded rows

// ---------------- kernel 1: combined bias+mask table ----------------
// g_bm[((w*3+h)*343 + i)*344 + j] = table[rpi[i,j]*3+h] + mask[w,i,j]
__global__ void bm_kernel(const int* __restrict__ rpi, const float* __restrict__ table,
                          const float* __restrict__ mask) {
    size_t idx = (size_t)blockIdx.x * blockDim.x + threadIdx.x;
    const size_t total = (size_t)NW_ * HEADS * N_ * PSW;
    if (idx >= total) return;
    int j  = (int)(idx % PSW);
    size_t rest = idx / PSW;
    int i  = (int)(rest % N_);
    int wh = (int)(rest / N_);
    int h  = wh % HEADS;
    int w  = wh / HEADS;
    float v = 0.0f;
    if (j < N_)
        v = table[rpi[i * N_ + j] * HEADS + h] + mask[((size_t)w * N_ + i) * N_ + j];
    g_bm[idx] = v;
}

// ---------------- GEMM core (k-major smem, vectorized operand loads) ----------------
__device__ __forceinline__ void gemm_core(const float* __restrict__ xg4,   // 128x96 tile
                                          const float* __restrict__ wg4,   // 96x96 slice
                                          float* xs_t, float* ws_t,
                                          float acc[8][6], int tid) {
    {
        const float4* xg = (const float4*)xg4;
        for (int i = tid; i < 128 * 24; i += 256) {
            int r = i / 24, c4 = i % 24;
            float4 v = xg[r * 24 + c4];
            xs_t[(c4 * 4 + 0) * 132 + r] = v.x;
            xs_t[(c4 * 4 + 1) * 132 + r] = v.y;
            xs_t[(c4 * 4 + 2) * 132 + r] = v.z;
            xs_t[(c4 * 4 + 3) * 132 + r] = v.w;
        }
    }
    {
        const float4* wg = (const float4*)wg4;
        for (int i = tid; i < 96 * 24; i += 256) {
            int r = i / 24, c4 = i % 24;
            float4 v = wg[r * 24 + c4];
            ws_t[(c4 * 4 + 0) * 100 + r] = v.x;
            ws_t[(c4 * 4 + 1) * 100 + r] = v.y;
            ws_t[(c4 * 4 + 2) * 100 + r] = v.z;
            ws_t[(c4 * 4 + 3) * 100 + r] = v.w;
        }
    }
    __syncthreads();

    const int tx = tid & 15, ty = tid >> 4;
#pragma unroll
    for (int i = 0; i < 8; i++)
#pragma unroll
        for (int j = 0; j < 6; j++) acc[i][j] = 0.0f;

#pragma unroll 4
    for (int k = 0; k < 96; k++) {
        float4 a0 = *(const float4*)&xs_t[k * 132 + ty * 8];
        float4 a1 = *(const float4*)&xs_t[k * 132 + ty * 8 + 4];
        float2 b0 = *(const float2*)&ws_t[k * 100 + tx * 6];
        float2 b1 = *(const float2*)&ws_t[k * 100 + tx * 6 + 2];
        float2 b2 = *(const float2*)&ws_t[k * 100 + tx * 6 + 4];
        float a[8] = {a0.x, a0.y, a0.z, a0.w, a1.x, a1.y, a1.z, a1.w};
        float b[6] = {b0.x, b0.y, b1.x, b1.y, b2.x, b2.y};
#pragma unroll
        for (int i = 0; i < 8; i++)
#pragma unroll
            for (int j = 0; j < 6; j++) acc[i][j] = fmaf(a[i], b[j], acc[i][j]);
    }
}

// ---------------- kernel 2: QKV GEMM ----------------
__global__ __launch_bounds__(256, 2) void qkv_gemm(const float* __restrict__ x,
                                                   const float* __restrict__ W,
                                                   const float* __restrict__ bias) {
    extern __shared__ float sm[];
    float* xs_t = sm;
    float* ws_t = sm + 96 * 132;
    const int tid   = threadIdx.x;
    const int which = blockIdx.y;
    const int m0    = blockIdx.x * 128;

    float acc[8][6];
    gemm_core(x + (size_t)m0 * 96, W + (size_t)which * 96 * 96, xs_t, ws_t, acc, tid);

    const int tx = tid & 15, ty = tid >> 4;
    float* base = (which == 0) ? g_q : (which == 1) ? g_k : g_v;
#pragma unroll
    for (int i = 0; i < 8; i++) {
        int m = m0 + ty * 8 + i;
        int bw = m / N_, n = m - bw * N_;
#pragma unroll
        for (int j = 0; j < 6; j++) {
            int c = tx * 6 + j;
            int h = c >> 5, d = c & 31;
            base[(((size_t)bw * HEADS + h) * N_ + n) * HD + d] = acc[i][j] + bias[which * 96 + c];
        }
    }
}

// ---------------- cp.async helpers ----------------
__device__ __forceinline__ void cp_async16(float* smem_dst, const float* gmem_src) {
    unsigned saddr = (unsigned)__cvta_generic_to_shared(smem_dst);
    asm volatile("cp.async.cg.shared.global [%0], [%1], 16;\n" :: "r"(saddr), "l"(gmem_src));
}
__device__ __forceinline__ void cp_async_commit() {
    asm volatile("cp.async.commit_group;\n" ::: "memory");
}
__device__ __forceinline__ void cp_async_wait0() {
    asm volatile("cp.async.wait_group 0;\n" ::: "memory");
}

// prefetch bm rows for tile i0 into ps rows (warp-owned). 86 float4 per row.
template<int RPW>
__device__ __forceinline__ void prefetch_bm(int i0, float* ps,
                                            const float* __restrict__ bmb,
                                            int ty, int tx) {
#pragma unroll
    for (int rr = 0; rr < RPW; rr++) {
        int i = i0 + ty * RPW + rr;
        if (i > N_ - 1) i = N_ - 1;                 // clamped rows (discarded later)
        const float* src = bmb + (size_t)i * PSW;
        float* dst = ps + (ty * 8 + rr) * PSW;
        cp_async16(dst + tx * 4,        src + tx * 4);
        cp_async16(dst + (tx + 32) * 4, src + (tx + 32) * 4);
        if (tx < 22)
            cp_async16(dst + (tx + 64) * 4, src + (tx + 64) * 4);
    }
    cp_async_commit();
}

// ---------------- attn tile worker ----------------
// ps row ownership is warp-constant: warp ty ALWAYS uses ps rows [ty*8, ty*8+RPW).
// bm for this tile has been prefetched into the same ps rows (read before overwrite).
template<int RPW>
__device__ __forceinline__ void attn_tile(int i0, float* sm,
                                          float scl, int b, int h, int ty, int tx) {
    float* ks = sm + KS_OFF;
    float* vs = sm + VS_OFF;
    float* qs = sm + QS_OFF;
    float* ps = sm + PS_OFF;

    // ---- Phase A: S = Q K^T ----
    float acc[RPW][11];
#pragma unroll
    for (int rr = 0; rr < RPW; rr++)
#pragma unroll
        for (int t = 0; t < 11; t++) acc[rr][t] = 0.0f;

#pragma unroll
    for (int d0 = 0; d0 < 32; d0 += 4) {
        float qa[RPW][4];
#pragma unroll
        for (int rr = 0; rr < RPW; rr++) {
            int row = i0 + ty * RPW + rr;
            row = (row < NROWS) ? row : 0;          // qs has NROWS rows
            float4 q4 = *(const float4*)&qs[row * 36 + d0];   // broadcast
            qa[rr][0] = q4.x; qa[rr][1] = q4.y; qa[rr][2] = q4.z; qa[rr][3] = q4.w;
        }
#pragma unroll
        for (int t = 0; t < 11; t++) {
            int j = tx + 32 * t;                     // rows >= NROWS read in-bounds junk; masked later
            float4 k4 = *(const float4*)&ks[j * 36 + d0];
#pragma unroll
            for (int rr = 0; rr < RPW; rr++) {
                acc[rr][t] = fmaf(qa[rr][0], k4.x, acc[rr][t]);
                acc[rr][t] = fmaf(qa[rr][1], k4.y, acc[rr][t]);
                acc[rr][t] = fmaf(qa[rr][2], k4.z, acc[rr][t]);
                acc[rr][t] = fmaf(qa[rr][3], k4.w, acc[rr][t]);
            }
        }
    }

    // ---- wait for this tile's bm prefetch, then softmax (warp-local rows) ----
    cp_async_wait0();
    __syncwarp();
#pragma unroll
    for (int rr = 0; rr < RPW; rr++) {
        const float* bmrow = ps + (ty * 8 + rr) * PSW;
        float bm[11];
#pragma unroll
        for (int t = 0; t < 11; t++) {
            int j = tx + 32 * t;
            bm[t] = (j < N_) ? bmrow[j] : -1e30f;
        }
        float mx = -1e30f;
#pragma unroll
        for (int t = 0; t < 11; t++) {
            int j = tx + 32 * t;
            float s = (j < N_) ? fmaf(acc[rr][t], scl, bm[t]) : -1e30f;
            acc[rr][t] = s;
            mx = fmaxf(mx, s);
        }
#pragma unroll
        for (int o = 16; o; o >>= 1) mx = fmaxf(mx, __shfl_xor_sync(0xffffffffu, mx, o));
        float sum = 0.0f;
#pragma unroll
        for (int t = 0; t < 11; t++) {
            int j = tx + 32 * t;
            float e = (j < N_) ? __expf(acc[rr][t] - mx) : 0.0f;
            acc[rr][t] = e;
            sum += e;
        }
#pragma unroll
        for (int o = 16; o; o >>= 1) sum += __shfl_xor_sync(0xffffffffu, sum, o);
        float inv = 1.0f / sum;
#pragma unroll
        for (int t = 0; t < 11; t++) {
            int j = tx + 32 * t;
            if (j < PSW)
                ps[(ty * 8 + rr) * PSW + j] = acc[rr][t] * inv;   // overwrite bm with p
        }
    }
    __syncwarp();

    // ---- Phase B: O = P V (lane = output dim) ----
    float o[RPW];
#pragma unroll
    for (int rr = 0; rr < RPW; rr++) o[rr] = 0.0f;

#pragma unroll 2
    for (int j0 = 0; j0 < PSW; j0 += 4) {
        float pa[RPW][4];
#pragma unroll
        for (int rr = 0; rr < RPW; rr++) {
            float4 p4 = *(const float4*)&ps[(ty * 8 + rr) * PSW + j0];  // broadcast
            pa[rr][0] = p4.x; pa[rr][1] = p4.y; pa[rr][2] = p4.z; pa[rr][3] = p4.w;
        }
#pragma unroll
        for (int jj = 0; jj < 4; jj++) {
            float vv = vs[(j0 + jj) * 32 + tx];
#pragma unroll
            for (int rr = 0; rr < RPW; rr++)
                o[rr] = fmaf(pa[rr][jj], vv, o[rr]);
        }
    }
#pragma unroll
    for (int rr = 0; rr < RPW; rr++) {
        int i = i0 + ty * RPW + rr;
        if (i < N_)
            g_ao[((size_t)b * N_ + i) * DIM_ + h * HD + tx] = o[rr];
    }
    __syncwarp();
}

// ---------------- kernel 3: attention ----------------
// smem: ks [344][36], vs [344][32], qs [344][36], ps [64][344] = 231168 B
__global__ __launch_bounds__(256) void attn_kernel(const float* __restrict__ logit_scale) {
    extern __shared__ float sm[];
    float* ks = sm + KS_OFF;
    float* vs = sm + VS_OFF;
    float* qs = sm + QS_OFF;
    float* ps = sm + PS_OFF;

    const int bx = blockIdx.x;
    const int b  = bx / HEADS;
    const int h  = bx - b * HEADS;
    const int w  = b & (NW_ - 1);
    const int tid = threadIdx.x;
    const int ty = tid >> 5, tx = tid & 31;

    const size_t bh = (size_t)b * HEADS + h;
    const float* qg = g_q + bh * N_ * HD;
    const float* kg = g_k + bh * N_ * HD;
    const float* vg = g_v + bh * N_ * HD;

    const float* bmb = g_bm + ((size_t)w * HEADS + h) * N_ * PSW;

    // tile-0 bm prefetch overlaps staging (ps untouched by staging; warp-private rows)
    prefetch_bm<8>(0, ps, bmb, ty, tx);

    // stage rows 0..343 (row 343 zero-filled), fused q/k L2 normalization
    for (int r = ty; r < NROWS; r += 8) {
        float qv = 0.f, kv = 0.f, vv = 0.f;
        if (r < N_) {
            int off = r * HD + tx;
            qv = qg[off]; kv = kg[off]; vv = vg[off];
        }
        float qss = qv * qv, kss = kv * kv;
#pragma unroll
        for (int o = 16; o; o >>= 1) {
            qss += __shfl_xor_sync(0xffffffffu, qss, o);
            kss += __shfl_xor_sync(0xffffffffu, kss, o);
        }
        float qinv = 1.0f / fmaxf(sqrtf(qss), 1e-12f);
        float kinv = 1.0f / fmaxf(sqrtf(kss), 1e-12f);
        qs[r * 36 + tx] = qv * qinv;
        ks[r * 36 + tx] = kv * kinv;
        vs[r * 32 + tx] = vv;
    }
    __syncthreads();

    const float scl = fminf(__expf(logit_scale[h]), 100.0f);

    // pipeline: prefetch(t) ... PhaseA(t) | wait | softmax(t) PhaseB(t) prefetch(t+1)
#pragma unroll 1
    for (int i0 = 0; i0 < 320; i0 += 64) {
        attn_tile<8>(i0, sm, scl, b, h, ty, tx);
        if (i0 + 64 < 320) prefetch_bm<8>(i0 + 64, ps, bmb, ty, tx);
        else               prefetch_bm<4>(320,     ps, bmb, ty, tx);
    }
    attn_tile<4>(320, sm, scl, b, h, ty, tx);
}

// ---------------- kernel 4: output projection ----------------
__global__ __launch_bounds__(256, 2) void proj_gemm(const float* __restrict__ W,
                                                    const float* __restrict__ bias,
                                                    float* __restrict__ out) {
    extern __shared__ float sm[];
    float* xs_t = sm;
    float* ws_t = sm + 96 * 132;
    const int tid = threadIdx.x;
    const int m0  = blockIdx.x * 128;

    float acc[8][6];
    gemm_core(g_ao + (size_t)m0 * 96, W, xs_t, ws_t, acc, tid);

    const int tx = tid & 15, ty = tid >> 4;
#pragma unroll
    for (int i = 0; i < 8; i++) {
        int m = m0 + ty * 8 + i;
#pragma unroll
        for (int j = 0; j < 6; j++) {
            int c = tx * 6 + j;
            out[(size_t)m * 96 + c] = acc[i][j] + bias[c];
        }
    }
}

// ---------------- launch ----------------
extern "C" void kernel_launch(void* const* d_in, const int* in_sizes, int n_in,
                              void* d_out, int out_size) {
    const float* x     = (const float*)d_in[0];
    const float* mask  = (const float*)d_in[1];
    const float* Wqkv  = (const float*)d_in[2];
    const float* bqkv  = (const float*)d_in[3];
    const float* Wproj = (const float*)d_in[4];
    const float* bproj = (const float*)d_in[5];
    const float* ls    = (const float*)d_in[6];
    const float* table = (const float*)d_in[7];
    const int*   rpi   = (const int*)d_in[8];
    float* out = (float*)d_out;

    const int smG = (96 * 132 + 96 * 100) * 4;   // 89088 B
    const int smA = SM_FLOATS * 4;               // 231168 B
    cudaFuncSetAttribute(qkv_gemm,  cudaFuncAttributeMaxDynamicSharedMemorySize, smG);
    cudaFuncSetAttribute(proj_gemm, cudaFuncAttributeMaxDynamicSharedMemorySize, smG);
    cudaFuncSetAttribute(attn_kernel, cudaFuncAttributeMaxDynamicSharedMemorySize, smA);

    const size_t bm_total = (size_t)NW_ * HEADS * N_ * PSW;
    bm_kernel<<<(unsigned)((bm_total + 255) / 256), 256>>>(rpi, table, mask);
    qkv_gemm<<<dim3(ROWS_TOT / 128, 3), 256, smG>>>(x, Wqkv, bqkv);
    attn_kernel<<<BW_ * HEADS, 256, smA>>>(ls);
    proj_gemm<<<ROWS_TOT / 128, 256, smG>>>(Wproj, bproj, out);
}

// round 9
// speedup vs baseline: 1.2525x; 1.0977x over previous
#include <cuda_runtime.h>
#include <math.h>

// ---------------- problem constants ----------------
#define BW_   512              // total windows
#define NW_   64               // mask batch
#define N_    343              // tokens per window
#define NROWS 344              // smem rows actually stored
#define PSW   344              // ps / bm row stride (mult of 4)
#define DIM_  96
#define HEADS 3
#define HD    32
#define NN_   (N_ * N_)        // 117649
#define ROWS_TOT (BW_ * N_)    // 175616

// smem float offsets for attn (ks stride 36, vs stride 32, qs stride 36, ps 64x344)
#define KS_OFF 0
#define VS_OFF (NROWS * 36)
#define QS_OFF (NROWS * 36 + NROWS * 32)
#define PS_OFF (2 * NROWS * 36 + NROWS * 32)
#define SM_FLOATS (PS_OFF + 64 * PSW)      // 57792 floats = 231168 B

// ---------------- device scratch ----------------
__device__ float g_q [BW_ * HEADS * N_ * HD];
__device__ float g_k [BW_ * HEADS * N_ * HD];
__device__ float g_v [BW_ * HEADS * N_ * HD];
__device__ float g_ao[ROWS_TOT * DIM_];
__device__ float g_bm[(size_t)NW_ * HEADS * N_ * PSW];   // bias+mask, padded rows

// ---------------- kernel 1: combined bias+mask table ----------------
__global__ void bm_kernel(const int* __restrict__ rpi, const float* __restrict__ table,
                          const float* __restrict__ mask) {
    size_t idx = (size_t)blockIdx.x * blockDim.x + threadIdx.x;
    const size_t total = (size_t)NW_ * HEADS * N_ * PSW;
    if (idx >= total) return;
    int j  = (int)(idx % PSW);
    size_t rest = idx / PSW;
    int i  = (int)(rest % N_);
    int wh = (int)(rest / N_);
    int h  = wh % HEADS;
    int w  = wh / HEADS;
    float v = 0.0f;
    if (j < N_)
        v = table[rpi[i * N_ + j] * HEADS + h] + mask[((size_t)w * N_ + i) * N_ + j];
    g_bm[idx] = v;
}

// ---------------- GEMM core (k-major smem, vectorized operand loads) ----------------
__device__ __forceinline__ void gemm_core(const float* __restrict__ xg4,   // 128x96 tile
                                          const float* __restrict__ wg4,   // 96x96 slice
                                          float* xs_t, float* ws_t,
                                          float acc[8][6], int tid) {
    {
        const float4* xg = (const float4*)xg4;
        for (int i = tid; i < 128 * 24; i += 256) {
            int r = i / 24, c4 = i % 24;
            float4 v = xg[r * 24 + c4];
            xs_t[(c4 * 4 + 0) * 132 + r] = v.x;
            xs_t[(c4 * 4 + 1) * 132 + r] = v.y;
            xs_t[(c4 * 4 + 2) * 132 + r] = v.z;
            xs_t[(c4 * 4 + 3) * 132 + r] = v.w;
        }
    }
    {
        const float4* wg = (const float4*)wg4;
        for (int i = tid; i < 96 * 24; i += 256) {
            int r = i / 24, c4 = i % 24;
            float4 v = wg[r * 24 + c4];
            ws_t[(c4 * 4 + 0) * 100 + r] = v.x;
            ws_t[(c4 * 4 + 1) * 100 + r] = v.y;
            ws_t[(c4 * 4 + 2) * 100 + r] = v.z;
            ws_t[(c4 * 4 + 3) * 100 + r] = v.w;
        }
    }
    __syncthreads();

    const int tx = tid & 15, ty = tid >> 4;
#pragma unroll
    for (int i = 0; i < 8; i++)
#pragma unroll
        for (int j = 0; j < 6; j++) acc[i][j] = 0.0f;

#pragma unroll 4
    for (int k = 0; k < 96; k++) {
        float4 a0 = *(const float4*)&xs_t[k * 132 + ty * 8];
        float4 a1 = *(const float4*)&xs_t[k * 132 + ty * 8 + 4];
        float2 b0 = *(const float2*)&ws_t[k * 100 + tx * 6];
        float2 b1 = *(const float2*)&ws_t[k * 100 + tx * 6 + 2];
        float2 b2 = *(const float2*)&ws_t[k * 100 + tx * 6 + 4];
        float a[8] = {a0.x, a0.y, a0.z, a0.w, a1.x, a1.y, a1.z, a1.w};
        float b[6] = {b0.x, b0.y, b1.x, b1.y, b2.x, b2.y};
#pragma unroll
        for (int i = 0; i < 8; i++)
#pragma unroll
            for (int j = 0; j < 6; j++) acc[i][j] = fmaf(a[i], b[j], acc[i][j]);
    }
}

// ---------------- kernel 2: QKV GEMM ----------------
__global__ __launch_bounds__(256, 2) void qkv_gemm(const float* __restrict__ x,
                                                   const float* __restrict__ W,
                                                   const float* __restrict__ bias) {
    extern __shared__ float sm[];
    float* xs_t = sm;
    float* ws_t = sm + 96 * 132;
    const int tid   = threadIdx.x;
    const int which = blockIdx.y;
    const int m0    = blockIdx.x * 128;

    float acc[8][6];
    gemm_core(x + (size_t)m0 * 96, W + (size_t)which * 96 * 96, xs_t, ws_t, acc, tid);

    const int tx = tid & 15, ty = tid >> 4;
    float* base = (which == 0) ? g_q : (which == 1) ? g_k : g_v;
#pragma unroll
    for (int i = 0; i < 8; i++) {
        int m = m0 + ty * 8 + i;
        int bw = m / N_, n = m - bw * N_;
#pragma unroll
        for (int j = 0; j < 6; j++) {
            int c = tx * 6 + j;
            int h = c >> 5, d = c & 31;
            base[(((size_t)bw * HEADS + h) * N_ + n) * HD + d] = acc[i][j] + bias[which * 96 + c];
        }
    }
}

// ---------------- cp.async helpers ----------------
__device__ __forceinline__ void cp_async16(float* smem_dst, const float* gmem_src) {
    unsigned saddr = (unsigned)__cvta_generic_to_shared(smem_dst);
    asm volatile("cp.async.cg.shared.global [%0], [%1], 16;\n" :: "r"(saddr), "l"(gmem_src));
}
__device__ __forceinline__ void cp_async_commit() {
    asm volatile("cp.async.commit_group;\n" ::: "memory");
}
__device__ __forceinline__ void cp_async_wait0() {
    asm volatile("cp.async.wait_group 0;\n" ::: "memory");
}

// prefetch bm rows for tile i0 into warp-owned ps rows (base ty*4). 86 float4/row.
template<int RPW>
__device__ __forceinline__ void prefetch_bm(int i0, float* ps,
                                            const float* __restrict__ bmb,
                                            int ty, int tx) {
#pragma unroll
    for (int rr = 0; rr < RPW; rr++) {
        int i = i0 + ty * RPW + rr;
        if (i > N_ - 1) i = N_ - 1;                 // clamped rows (discarded later)
        const float* src = bmb + (size_t)i * PSW;
        float* dst = ps + (ty * 4 + rr) * PSW;
        cp_async16(dst + tx * 4,        src + tx * 4);
        cp_async16(dst + (tx + 32) * 4, src + (tx + 32) * 4);
        if (tx < 22)
            cp_async16(dst + (tx + 64) * 4, src + (tx + 64) * 4);
    }
    cp_async_commit();
}

// ---------------- attn tile worker (16 warps, RPW rows per warp) ----------------
// ps row ownership is warp-constant: warp ty ALWAYS uses ps rows [ty*4, ty*4+RPW).
template<int RPW>
__device__ __forceinline__ void attn_tile(int i0, float* sm,
                                          float scl, int b, int h, int ty, int tx) {
    float* ks = sm + KS_OFF;
    float* vs = sm + VS_OFF;
    float* qs = sm + QS_OFF;
    float* ps = sm + PS_OFF;

    // ---- Phase A: S = Q K^T ----
    float acc[RPW][11];
#pragma unroll
    for (int rr = 0; rr < RPW; rr++)
#pragma unroll
        for (int t = 0; t < 11; t++) acc[rr][t] = 0.0f;

#pragma unroll
    for (int d0 = 0; d0 < 32; d0 += 4) {
        float qa[RPW][4];
#pragma unroll
        for (int rr = 0; rr < RPW; rr++) {
            int row = i0 + ty * RPW + rr;
            row = (row < NROWS) ? row : 0;          // qs has NROWS rows
            float4 q4 = *(const float4*)&qs[row * 36 + d0];   // broadcast
            qa[rr][0] = q4.x; qa[rr][1] = q4.y; qa[rr][2] = q4.z; qa[rr][3] = q4.w;
        }
#pragma unroll
        for (int t = 0; t < 11; t++) {
            int j = tx + 32 * t;                     // j>=NROWS reads in-bounds junk; masked later
            float4 k4 = *(const float4*)&ks[j * 36 + d0];
#pragma unroll
            for (int rr = 0; rr < RPW; rr++) {
                acc[rr][t] = fmaf(qa[rr][0], k4.x, acc[rr][t]);
                acc[rr][t] = fmaf(qa[rr][1], k4.y, acc[rr][t]);
                acc[rr][t] = fmaf(qa[rr][2], k4.z, acc[rr][t]);
                acc[rr][t] = fmaf(qa[rr][3], k4.w, acc[rr][t]);
            }
        }
    }

    // ---- wait for this tile's bm prefetch, then softmax (warp-local rows) ----
    cp_async_wait0();
    __syncwarp();
#pragma unroll
    for (int rr = 0; rr < RPW; rr++) {
        const float* bmrow = ps + (ty * 4 + rr) * PSW;
        float bm[11];
#pragma unroll
        for (int t = 0; t < 11; t++) {
            int j = tx + 32 * t;
            bm[t] = (j < N_) ? bmrow[j] : -1e30f;
        }
        float mx = -1e30f;
#pragma unroll
        for (int t = 0; t < 11; t++) {
            int j = tx + 32 * t;
            float s = (j < N_) ? fmaf(acc[rr][t], scl, bm[t]) : -1e30f;
            acc[rr][t] = s;
            mx = fmaxf(mx, s);
        }
#pragma unroll
        for (int o = 16; o; o >>= 1) mx = fmaxf(mx, __shfl_xor_sync(0xffffffffu, mx, o));
        float sum = 0.0f;
#pragma unroll
        for (int t = 0; t < 11; t++) {
            int j = tx + 32 * t;
            float e = (j < N_) ? __expf(acc[rr][t] - mx) : 0.0f;
            acc[rr][t] = e;
            sum += e;
        }
#pragma unroll
        for (int o = 16; o; o >>= 1) sum += __shfl_xor_sync(0xffffffffu, sum, o);
        float inv = 1.0f / sum;
#pragma unroll
        for (int t = 0; t < 11; t++) {
            int j = tx + 32 * t;
            if (j < PSW)
                ps[(ty * 4 + rr) * PSW + j] = acc[rr][t] * inv;   // overwrite bm with p
        }
    }
    __syncwarp();

    // ---- Phase B: O = P V (lane = output dim) ----
    float o[RPW];
#pragma unroll
    for (int rr = 0; rr < RPW; rr++) o[rr] = 0.0f;

#pragma unroll 2
    for (int j0 = 0; j0 < PSW; j0 += 4) {
        float pa[RPW][4];
#pragma unroll
        for (int rr = 0; rr < RPW; rr++) {
            float4 p4 = *(const float4*)&ps[(ty * 4 + rr) * PSW + j0];  // broadcast
            pa[rr][0] = p4.x; pa[rr][1] = p4.y; pa[rr][2] = p4.z; pa[rr][3] = p4.w;
        }
#pragma unroll
        for (int jj = 0; jj < 4; jj++) {
            float vv = vs[(j0 + jj) * 32 + tx];
#pragma unroll
            for (int rr = 0; rr < RPW; rr++)
                o[rr] = fmaf(pa[rr][jj], vv, o[rr]);
        }
    }
#pragma unroll
    for (int rr = 0; rr < RPW; rr++) {
        int i = i0 + ty * RPW + rr;
        if (i < N_)
            g_ao[((size_t)b * N_ + i) * DIM_ + h * HD + tx] = o[rr];
    }
    __syncwarp();
}

// ---------------- kernel 3: attention (512 threads = 16 warps = 4/SMSP) ----------------
// smem: ks [344][36], vs [344][32], qs [344][36], ps [64][344] = 231168 B
__global__ __launch_bounds__(512) void attn_kernel(const float* __restrict__ logit_scale) {
    extern __shared__ float sm[];
    float* ks = sm + KS_OFF;
    float* vs = sm + VS_OFF;
    float* qs = sm + QS_OFF;
    float* ps = sm + PS_OFF;

    const int bx = blockIdx.x;
    const int b  = bx / HEADS;
    const int h  = bx - b * HEADS;
    const int w  = b & (NW_ - 1);
    const int tid = threadIdx.x;
    const int ty = tid >> 5, tx = tid & 31;   // ty: 0..15

    const size_t bh = (size_t)b * HEADS + h;
    const float* qg = g_q + bh * N_ * HD;
    const float* kg = g_k + bh * N_ * HD;
    const float* vg = g_v + bh * N_ * HD;

    const float* bmb = g_bm + ((size_t)w * HEADS + h) * N_ * PSW;

    // tile-0 bm prefetch overlaps staging (ps untouched by staging; warp-private rows)
    prefetch_bm<4>(0, ps, bmb, ty, tx);

    // stage rows 0..343 (row 343 zero-filled), fused q/k L2 normalization
    for (int r = ty; r < NROWS; r += 16) {
        float qv = 0.f, kv = 0.f, vv = 0.f;
        if (r < N_) {
            int off = r * HD + tx;
            qv = qg[off]; kv = kg[off]; vv = vg[off];
        }
        float qss = qv * qv, kss = kv * kv;
#pragma unroll
        for (int o = 16; o; o >>= 1) {
            qss += __shfl_xor_sync(0xffffffffu, qss, o);
            kss += __shfl_xor_sync(0xffffffffu, kss, o);
        }
        float qinv = 1.0f / fmaxf(sqrtf(qss), 1e-12f);
        float kinv = 1.0f / fmaxf(sqrtf(kss), 1e-12f);
        qs[r * 36 + tx] = qv * qinv;
        ks[r * 36 + tx] = kv * kinv;
        vs[r * 32 + tx] = vv;
    }
    __syncthreads();

    const float scl = fminf(__expf(logit_scale[h]), 100.0f);

    // pipeline: prefetch(t) ... PhaseA(t) | wait | softmax(t) PhaseB(t) prefetch(t+1)
#pragma unroll 1
    for (int i0 = 0; i0 < 320; i0 += 64) {
        attn_tile<4>(i0, sm, scl, b, h, ty, tx);
        if (i0 + 64 < 320) prefetch_bm<4>(i0 + 64, ps, bmb, ty, tx);
        else               prefetch_bm<2>(320,     ps, bmb, ty, tx);
    }
    attn_tile<2>(320, sm, scl, b, h, ty, tx);   // rows 320..351 (tail)
}

// ---------------- kernel 4: output projection ----------------
__global__ __launch_bounds__(256, 2) void proj_gemm(const float* __restrict__ W,
                                                    const float* __restrict__ bias,
                                                    float* __restrict__ out) {
    extern __shared__ float sm[];
    float* xs_t = sm;
    float* ws_t = sm + 96 * 132;
    const int tid = threadIdx.x;
    const int m0  = blockIdx.x * 128;

    float acc[8][6];
    gemm_core(g_ao + (size_t)m0 * 96, W, xs_t, ws_t, acc, tid);

    const int tx = tid & 15, ty = tid >> 4;
#pragma unroll
    for (int i = 0; i < 8; i++) {
        int m = m0 + ty * 8 + i;
#pragma unroll
        for (int j = 0; j < 6; j++) {
            int c = tx * 6 + j;
            out[(size_t)m * 96 + c] = acc[i][j] + bias[c];
        }
    }
}

// ---------------- launch ----------------
extern "C" void kernel_launch(void* const* d_in, const int* in_sizes, int n_in,
                              void* d_out, int out_size) {
    const float* x     = (const float*)d_in[0];
    const float* mask  = (const float*)d_in[1];
    const float* Wqkv  = (const float*)d_in[2];
    const float* bqkv  = (const float*)d_in[3];
    const float* Wproj = (const float*)d_in[4];
    const float* bproj = (const float*)d_in[5];
    const float* ls    = (const float*)d_in[6];
    const float* table = (const float*)d_in[7];
    const int*   rpi   = (const int*)d_in[8];
    float* out = (float*)d_out;

    const int smG = (96 * 132 + 96 * 100) * 4;   // 89088 B
    const int smA = SM_FLOATS * 4;               // 231168 B
    cudaFuncSetAttribute(qkv_gemm,  cudaFuncAttributeMaxDynamicSharedMemorySize, smG);
    cudaFuncSetAttribute(proj_gemm, cudaFuncAttributeMaxDynamicSharedMemorySize, smG);
    cudaFuncSetAttribute(attn_kernel, cudaFuncAttributeMaxDynamicSharedMemorySize, smA);

    const size_t bm_total = (size_t)NW_ * HEADS * N_ * PSW;
    bm_kernel<<<(unsigned)((bm_total + 255) / 256), 256>>>(rpi, table, mask);
    qkv_gemm<<<dim3(ROWS_TOT / 128, 3), 256, smG>>>(x, Wqkv, bqkv);
    attn_kernel<<<BW_ * HEADS, 512, smA>>>(ls);
    proj_gemm<<<ROWS_TOT / 128, 256, smG>>>(Wproj, bproj, out);
}